// round 1
// baseline (speedup 1.0000x reference)
#include <cuda_runtime.h>
#include <math.h>
#include <stdint.h>

// Problem constants
#define BB 2
#define SS 576
#define FF 16
#define DD 512
#define HH 8
#define CC 64
#define MROWS (BB*SS*FF)   // 18432

// Scratch (allocation-free: __device__ globals)
__device__ float g_q[MROWS*DD];
__device__ float g_k[MROWS*DD];
__device__ float g_v[MROWS*DD];
__device__ float g_att[MROWS*DD];
__device__ int   g_frames[BB][FF];
__device__ int   g_df[BB];

// ---------------------------------------------------------------------------
// Build kept-frame index list per batch from drop_mask (int32, shape (B, F-2))
// dk frames = [0, 1] ++ [f for f in 2..F-1 if mask[f-2]==0]
// ---------------------------------------------------------------------------
__global__ void build_frames_kernel(const int* __restrict__ mask)
{
    if (threadIdx.x == 0 && blockIdx.x == 0) {
        for (int b = 0; b < BB; b++) {
            int n = 0;
            g_frames[b][n++] = 0;
            g_frames[b][n++] = 1;
            for (int f = 2; f < FF; f++)
                if (mask[b*(FF-2) + (f-2)] == 0) g_frames[b][n++] = f;
            g_df[b] = n;
        }
    }
}

// ---------------------------------------------------------------------------
// GEMM: C[M,512] = A[M,512] @ W[512,512] (+ bias), fp32.
// 64x64 tile, BK=16, 256 threads, 4x4 register micro-tile, float4 smem loads.
// ---------------------------------------------------------------------------
__global__ __launch_bounds__(256) void gemm512_kernel(
    const float* __restrict__ A, const float* __restrict__ W,
    float* __restrict__ C, const float* __restrict__ bias)
{
    __shared__ float As[16][64];   // [k][m]
    __shared__ float Ws[16][64];   // [k][n]

    const int bm = blockIdx.x * 64;
    const int bn = blockIdx.y * 64;
    const int tid = threadIdx.x;
    const int ty = tid >> 4;       // 0..15 -> rows ty*4..+3
    const int tx = tid & 15;       // 0..15 -> cols tx*4..+3

    const int ar  = tid >> 2;      // 0..63 A-tile row
    const int ac4 = tid & 3;       // 0..3  A-tile float4 col
    const int wr  = tid >> 4;      // 0..15 W-tile row
    const int wc4 = tid & 15;      // 0..15 W-tile float4 col

    const float* Aptr = A + (size_t)(bm + ar) * DD + ac4 * 4;
    const float* Wptr = W + (size_t)wr * DD + bn + wc4 * 4;

    float acc[4][4];
#pragma unroll
    for (int i = 0; i < 4; i++)
#pragma unroll
        for (int j = 0; j < 4; j++) acc[i][j] = 0.f;

    for (int k0 = 0; k0 < DD; k0 += 16) {
        float4 av = *(const float4*)(Aptr + k0);
        float4 wv = *(const float4*)(Wptr + (size_t)k0 * DD);
        __syncthreads();
        As[ac4*4+0][ar] = av.x; As[ac4*4+1][ar] = av.y;
        As[ac4*4+2][ar] = av.z; As[ac4*4+3][ar] = av.w;
        *(float4*)&Ws[wr][wc4*4] = wv;
        __syncthreads();
#pragma unroll
        for (int kk = 0; kk < 16; kk++) {
            float4 a = *(const float4*)&As[kk][ty*4];
            float4 w = *(const float4*)&Ws[kk][tx*4];
            float af[4] = {a.x, a.y, a.z, a.w};
            float wf[4] = {w.x, w.y, w.z, w.w};
#pragma unroll
            for (int i = 0; i < 4; i++)
#pragma unroll
                for (int j = 0; j < 4; j++)
                    acc[i][j] += af[i] * wf[j];
        }
    }

    float4 bv = make_float4(0.f, 0.f, 0.f, 0.f);
    if (bias) bv = *(const float4*)&bias[bn + tx*4];
#pragma unroll
    for (int i = 0; i < 4; i++) {
        float4 o;
        o.x = acc[i][0] + bv.x; o.y = acc[i][1] + bv.y;
        o.z = acc[i][2] + bv.z; o.w = acc[i][3] + bv.w;
        *(float4*)&C[(size_t)(bm + ty*4 + i) * DD + bn + tx*4] = o;
    }
}

// ---------------------------------------------------------------------------
// Flash attention, fp32. 64-query x 64-key tiles, online softmax.
// MODE 0 (ress): per-frame self attention, frames 1..F-1, keys = S.
// MODE 1 (resq): frame-0 queries over gathered frames, keys = S*df.
// smem: Qs (c-major), KP (K as [c][k], reused as P [k][q]), Vs ([k][c]) = 48KB.
// ---------------------------------------------------------------------------
template<int MODE>
__global__ __launch_bounds__(256) void attn_kernel(
    const float* __restrict__ Qg, const float* __restrict__ Kg,
    const float* __restrict__ Vg, float* __restrict__ Og)
{
    __shared__ float Qs[CC][64];
    __shared__ float KP[64][64];
    __shared__ float Vs[64][CC];

    const int tid = threadIdx.x;
    const int ty = tid >> 4;   // row group 0..15
    const int tx = tid & 15;   // col group 0..15
    const int q0 = blockIdx.x * 64;

    int b, h, f, n_tiles, df = 1, qf;
    if (MODE == 0) {
        int y = blockIdx.y;            // 0..B*(F-1)*H-1 = 0..239
        b = y / ((FF-1) * HH);
        int r = y % ((FF-1) * HH);
        f = 1 + r / HH;
        h = r % HH;
        qf = f;
        n_tiles = SS / 64;
    } else {
        int y = blockIdx.y;            // 0..B*H-1 = 0..15
        b = y >> 3;
        h = y & 7;
        qf = 0;
        f = 0;
        df = g_df[b];
        n_tiles = (SS / 64) * df;      // S*df keys, always divisible by 64
    }

    const int ll = tid >> 2;   // 0..63 row within tile for loads
    const int c4 = tid & 3;    // 0..3

    // Load Q tile transposed: Qs[c][q]
    {
        size_t qrow = ((size_t)(b*SS + q0 + ll) * FF + qf) * DD + h * CC;
#pragma unroll
        for (int u = 0; u < 4; u++) {
            int cb = c4 * 16 + u * 4;
            float4 t = *(const float4*)&Qg[qrow + cb];
            Qs[cb+0][ll] = t.x; Qs[cb+1][ll] = t.y;
            Qs[cb+2][ll] = t.z; Qs[cb+3][ll] = t.w;
        }
    }

    float acc_o[4][4];
    float m_run[4], l_run[4];
#pragma unroll
    for (int i = 0; i < 4; i++) {
        m_run[i] = -1e30f; l_run[i] = 0.f;
#pragma unroll
        for (int j = 0; j < 4; j++) acc_o[i][j] = 0.f;
    }

    const float SC = 0.125f;   // 1/sqrt(C)

    for (int kt = 0; kt < n_tiles; kt++) {
        __syncthreads();   // previous PV done reading KP/Vs; Q visible on kt=0
        // Load K tile transposed into KP[c][k], V tile into Vs[k][c]
        {
            int kg = kt * 64 + ll;
            int sk, fk;
            if (MODE == 0) { sk = kg; fk = f; }
            else           { sk = kg / df; fk = g_frames[b][kg - sk*df]; }
            size_t krow = ((size_t)(b*SS + sk) * FF + fk) * DD + h * CC;
#pragma unroll
            for (int u = 0; u < 4; u++) {
                int cb = c4 * 16 + u * 4;
                float4 t  = *(const float4*)&Kg[krow + cb];
                KP[cb+0][ll] = t.x; KP[cb+1][ll] = t.y;
                KP[cb+2][ll] = t.z; KP[cb+3][ll] = t.w;
                float4 tv = *(const float4*)&Vg[krow + cb];
                *(float4*)&Vs[ll][cb] = tv;
            }
        }
        __syncthreads();

        // S = Q K^T (64x64, over c)
        float s[4][4];
#pragma unroll
        for (int i = 0; i < 4; i++)
#pragma unroll
            for (int j = 0; j < 4; j++) s[i][j] = 0.f;
#pragma unroll 8
        for (int c = 0; c < CC; c++) {
            float4 a  = *(const float4*)&Qs[c][ty*4];
            float4 kk = *(const float4*)&KP[c][tx*4];
            float af[4] = {a.x, a.y, a.z, a.w};
            float kf[4] = {kk.x, kk.y, kk.z, kk.w};
#pragma unroll
            for (int i = 0; i < 4; i++)
#pragma unroll
                for (int j = 0; j < 4; j++)
                    s[i][j] += af[i] * kf[j];
        }

        // Online softmax per query row (row group = 16 lanes, shfl width 16)
#pragma unroll
        for (int i = 0; i < 4; i++) {
            float m = fmaxf(fmaxf(s[i][0], s[i][1]), fmaxf(s[i][2], s[i][3]));
#pragma unroll
            for (int off = 8; off >= 1; off >>= 1)
                m = fmaxf(m, __shfl_xor_sync(0xffffffffu, m, off, 16));
            float mn = fmaxf(m_run[i], m * SC);
            float alpha = __expf(m_run[i] - mn);
            float ls = 0.f;
#pragma unroll
            for (int j = 0; j < 4; j++) {
                float e = __expf(s[i][j] * SC - mn);
                s[i][j] = e;
                ls += e;
            }
#pragma unroll
            for (int off = 8; off >= 1; off >>= 1)
                ls += __shfl_xor_sync(0xffffffffu, ls, off, 16);
            l_run[i] = l_run[i] * alpha + ls;
            m_run[i] = mn;
#pragma unroll
            for (int j = 0; j < 4; j++) acc_o[i][j] *= alpha;
        }

        __syncthreads();   // all threads finished reading KP as K
        // Store P into KP as [k][q]
#pragma unroll
        for (int i = 0; i < 4; i++)
#pragma unroll
            for (int j = 0; j < 4; j++)
                KP[tx*4 + j][ty*4 + i] = s[i][j];
        __syncthreads();

        // O += P @ V
#pragma unroll 8
        for (int kk = 0; kk < 64; kk++) {
            float4 p  = *(const float4*)&KP[kk][ty*4];
            float4 vv = *(const float4*)&Vs[kk][tx*4];
            float pf[4] = {p.x, p.y, p.z, p.w};
            float vf[4] = {vv.x, vv.y, vv.z, vv.w};
#pragma unroll
            for (int i = 0; i < 4; i++)
#pragma unroll
                for (int j = 0; j < 4; j++)
                    acc_o[i][j] += pf[i] * vf[j];
        }
    }

    // Epilogue: normalize, write to g_att frame slot
    const int of = (MODE == 0) ? f : 0;
#pragma unroll
    for (int i = 0; i < 4; i++) {
        float inv = 1.0f / l_run[i];
        float4 o;
        o.x = acc_o[i][0] * inv; o.y = acc_o[i][1] * inv;
        o.z = acc_o[i][2] * inv; o.w = acc_o[i][3] * inv;
        *(float4*)&Og[((size_t)(b*SS + q0 + ty*4 + i) * FF + of) * DD + h*CC + tx*4] = o;
    }
}

// ---------------------------------------------------------------------------
// kernel_launch: graph-capturable sequence on the default stream.
// ---------------------------------------------------------------------------
extern "C" void kernel_launch(void* const* d_in, const int* in_sizes, int n_in,
                              void* d_out, int out_size)
{
    const float* x    = (const float*)d_in[0];
    const int*   mask = (const int*)  d_in[1];   // drop_mask (int32)
    const float* Wq   = (const float*)d_in[2];
    const float* Wk   = (const float*)d_in[3];
    const float* Wv   = (const float*)d_in[4];
    const float* Wout = (const float*)d_in[5];
    const float* bout = (const float*)d_in[6];
    float* out = (float*)d_out;

    float *q, *k, *v, *att;
    cudaGetSymbolAddress((void**)&q,   g_q);
    cudaGetSymbolAddress((void**)&k,   g_k);
    cudaGetSymbolAddress((void**)&v,   g_v);
    cudaGetSymbolAddress((void**)&att, g_att);

    build_frames_kernel<<<1, 32>>>(mask);

    dim3 ggrid(MROWS / 64, DD / 64);   // (288, 8)
    gemm512_kernel<<<ggrid, 256>>>(x, Wq, q, nullptr);
    gemm512_kernel<<<ggrid, 256>>>(x, Wk, k, nullptr);
    gemm512_kernel<<<ggrid, 256>>>(x, Wv, v, nullptr);

    // ress: per-frame self attention, frames 1..15
    attn_kernel<0><<<dim3(SS / 64, BB * (FF-1) * HH), 256>>>(q, k, v, att);
    // resq: frame-0 queries over gathered key/value frames
    attn_kernel<1><<<dim3(SS / 64, BB * HH), 256>>>(q, k, v, att);

    // output projection + bias
    gemm512_kernel<<<ggrid, 256>>>(att, Wout, out, bout);
}

// round 2
// speedup vs baseline: 2.4363x; 2.4363x over previous
#include <cuda_runtime.h>
#include <math.h>
#include <stdint.h>

// Problem constants
#define BB 2
#define SS 576
#define FF 16
#define DD 512
#define HH 8
#define CC 64
#define MROWS (BB*SS*FF)   // 18432

// Scratch (allocation-free: __device__ globals)
__device__ float g_q[MROWS*DD];
__device__ float g_k[MROWS*DD];
__device__ float g_v[MROWS*DD];
__device__ float g_att[MROWS*DD];
__device__ int   g_frames[BB][FF];
__device__ int   g_df[BB];

__device__ __forceinline__ float to_tf32(float x) {
    float r;
    asm("cvt.rna.tf32.f32 %0, %1;" : "=f"(r) : "f"(x));
    return r;
}

// m16n8k8 tf32 MMA, fp32 accumulate. Fragment layout (lane l, g=l/4, t=l%4):
//  A(16x8): a0=A[g][t] a1=A[g+8][t] a2=A[g][t+4] a3=A[g+8][t+4]
//  B(8x8):  b0=B[t][g] b1=B[t+4][g]
//  D(16x8): d0=D[g][2t] d1=D[g][2t+1] d2=D[g+8][2t] d3=D[g+8][2t+1]
__device__ __forceinline__ void mma_tf32(float d[4], const uint32_t a[4], const uint32_t b[2]) {
    asm("mma.sync.aligned.m16n8k8.row.col.f32.tf32.tf32.f32 "
        "{%0,%1,%2,%3}, {%4,%5,%6,%7}, {%8,%9}, {%0,%1,%2,%3};"
        : "+f"(d[0]), "+f"(d[1]), "+f"(d[2]), "+f"(d[3])
        : "r"(a[0]), "r"(a[1]), "r"(a[2]), "r"(a[3]),
          "r"(b[0]), "r"(b[1]));
}

// ---------------------------------------------------------------------------
// Build kept-frame index list per batch from drop_mask (int32, shape (B, F-2))
// ---------------------------------------------------------------------------
__global__ void build_frames_kernel(const int* __restrict__ mask)
{
    if (threadIdx.x == 0 && blockIdx.x == 0) {
        for (int b = 0; b < BB; b++) {
            int n = 0;
            g_frames[b][n++] = 0;
            g_frames[b][n++] = 1;
            for (int f = 2; f < FF; f++)
                if (mask[b*(FF-2) + (f-2)] == 0) g_frames[b][n++] = f;
            g_df[b] = n;
        }
    }
}

// ---------------------------------------------------------------------------
// tf32 MMA GEMM: C[M,512] = A[M,512] @ W[512,512] (+ bias).
// Block 128x128, KC=16, 256 threads (8 warps: 4m x 2n), warp tile 32x64.
// ---------------------------------------------------------------------------
__global__ __launch_bounds__(256) void gemm_tf32_kernel(
    const float* __restrict__ A, const float* __restrict__ W,
    float* __restrict__ C, const float* __restrict__ bias)
{
    __shared__ float As[128][20];    // [m][k], pad 4 (conflict-free frag reads)
    __shared__ float Bs[16][136];    // [k][n], pad 8

    const int tid = threadIdx.x;
    const int lid = tid & 31, wid = tid >> 5;
    const int gID = lid >> 2, ct = lid & 3;
    const int warpM = wid >> 1;      // 0..3
    const int warpN = wid & 1;       // 0..1
    const int bm = blockIdx.x * 128;
    const int bn = blockIdx.y * 128;

    // Tile-load assignments (float4 granularity)
    // A tile 128x16 = 512 float4: idx -> row=idx>>2, c4=idx&3
    // B tile 16x128 = 512 float4: idx -> k=idx>>5, n4=idx&31
    const int a_row0 = tid >> 2,        a_c4 = tid & 3;
    const int a_row1 = (tid + 256) >> 2;
    const int b_k0   = tid >> 5,        b_n4 = tid & 31;
    const int b_k1   = (tid + 256) >> 5;

    const float* Ap0 = A + (size_t)(bm + a_row0) * DD + a_c4 * 4;
    const float* Ap1 = A + (size_t)(bm + a_row1) * DD + a_c4 * 4;
    const float* Bp0 = W + (size_t)b_k0 * DD + bn + b_n4 * 4;
    const float* Bp1 = W + (size_t)b_k1 * DD + bn + b_n4 * 4;

    float acc[2][8][4];
#pragma unroll
    for (int mf = 0; mf < 2; mf++)
#pragma unroll
        for (int nf = 0; nf < 8; nf++)
#pragma unroll
            for (int r = 0; r < 4; r++) acc[mf][nf][r] = 0.f;

    float4 ra0 = *(const float4*)(Ap0);
    float4 ra1 = *(const float4*)(Ap1);
    float4 rb0 = *(const float4*)(Bp0);
    float4 rb1 = *(const float4*)(Bp1);

    for (int k0 = 0; k0 < DD; k0 += 16) {
        __syncthreads();
        As[a_row0][a_c4*4+0] = to_tf32(ra0.x); As[a_row0][a_c4*4+1] = to_tf32(ra0.y);
        As[a_row0][a_c4*4+2] = to_tf32(ra0.z); As[a_row0][a_c4*4+3] = to_tf32(ra0.w);
        As[a_row1][a_c4*4+0] = to_tf32(ra1.x); As[a_row1][a_c4*4+1] = to_tf32(ra1.y);
        As[a_row1][a_c4*4+2] = to_tf32(ra1.z); As[a_row1][a_c4*4+3] = to_tf32(ra1.w);
        Bs[b_k0][b_n4*4+0] = to_tf32(rb0.x); Bs[b_k0][b_n4*4+1] = to_tf32(rb0.y);
        Bs[b_k0][b_n4*4+2] = to_tf32(rb0.z); Bs[b_k0][b_n4*4+3] = to_tf32(rb0.w);
        Bs[b_k1][b_n4*4+0] = to_tf32(rb1.x); Bs[b_k1][b_n4*4+1] = to_tf32(rb1.y);
        Bs[b_k1][b_n4*4+2] = to_tf32(rb1.z); Bs[b_k1][b_n4*4+3] = to_tf32(rb1.w);
        __syncthreads();

        if (k0 + 16 < DD) {
            ra0 = *(const float4*)(Ap0 + k0 + 16);
            ra1 = *(const float4*)(Ap1 + k0 + 16);
            rb0 = *(const float4*)(Bp0 + (size_t)(k0 + 16) * DD);
            rb1 = *(const float4*)(Bp1 + (size_t)(k0 + 16) * DD);
        }

#pragma unroll
        for (int kc = 0; kc < 16; kc += 8) {
            uint32_t afr[2][4];
#pragma unroll
            for (int mf = 0; mf < 2; mf++) {
                int m = warpM * 32 + mf * 16;
                afr[mf][0] = __float_as_uint(As[m + gID    ][kc + ct    ]);
                afr[mf][1] = __float_as_uint(As[m + gID + 8][kc + ct    ]);
                afr[mf][2] = __float_as_uint(As[m + gID    ][kc + ct + 4]);
                afr[mf][3] = __float_as_uint(As[m + gID + 8][kc + ct + 4]);
            }
#pragma unroll
            for (int nf = 0; nf < 8; nf++) {
                int n = warpN * 64 + nf * 8 + gID;
                uint32_t bfr[2];
                bfr[0] = __float_as_uint(Bs[kc + ct    ][n]);
                bfr[1] = __float_as_uint(Bs[kc + ct + 4][n]);
                mma_tf32(acc[0][nf], afr[0], bfr);
                mma_tf32(acc[1][nf], afr[1], bfr);
            }
        }
    }

    // Epilogue
#pragma unroll
    for (int mf = 0; mf < 2; mf++) {
        int r = bm + warpM * 32 + mf * 16 + gID;
#pragma unroll
        for (int nf = 0; nf < 8; nf++) {
            int cidx = bn + warpN * 64 + nf * 8 + ct * 2;
            float b0 = 0.f, b1 = 0.f;
            if (bias) { b0 = bias[cidx]; b1 = bias[cidx + 1]; }
            float2 v0 = make_float2(acc[mf][nf][0] + b0, acc[mf][nf][1] + b1);
            float2 v1 = make_float2(acc[mf][nf][2] + b0, acc[mf][nf][3] + b1);
            *(float2*)&C[(size_t)r * DD + cidx] = v0;
            *(float2*)&C[(size_t)(r + 8) * DD + cidx] = v1;
        }
    }
}

// ---------------------------------------------------------------------------
// Flash attention with tf32 MMA. 64q x 64k tiles, 128 threads (4 warps).
// Each warp owns 16 q-rows and the full 64-key range (softmax stays in-warp).
// Q fragments in registers (pre-scaled by 1/sqrt(C)); K^T and V in smem;
// P re-fragments through the K buffer (aliased).
// MODE 0 (ress): per-frame self attention. MODE 1 (resq): gathered frames.
// ---------------------------------------------------------------------------
template<int MODE>
__global__ __launch_bounds__(128) void attn_mma_kernel(
    const float* __restrict__ Qg, const float* __restrict__ Kg,
    const float* __restrict__ Vg, float* __restrict__ Og)
{
    __shared__ float KPs[64][68];   // K as [c][key]; reused as P [q][k]
    __shared__ float Vs[64][68];    // [key][c]

    const int tid = threadIdx.x;
    const int lid = tid & 31, w = tid >> 5;
    const int gID = lid >> 2, ct = lid & 3;
    const int q0 = blockIdx.x * 64;

    int b, h, f, qf, df = 1, n_tiles;
    if (MODE == 0) {
        int y = blockIdx.y;            // 0..B*(F-1)*H-1
        b = y / ((FF-1) * HH);
        int r = y % ((FF-1) * HH);
        f = 1 + r / HH;
        h = r % HH;
        qf = f;
        n_tiles = SS / 64;
    } else {
        int y = blockIdx.y;            // 0..B*H-1
        b = y >> 3;
        h = y & 7;
        qf = 0; f = 0;
        df = g_df[b];
        n_tiles = (SS / 64) * df;
    }

    // Q fragments in registers (rows w*16+gID, +8), pre-scaled by 1/8
    uint32_t qa[8][4];
    {
        const int r0 = q0 + w * 16 + gID;
        const size_t base0 = ((size_t)(b*SS + r0    ) * FF + qf) * DD + h * CC;
        const size_t base1 = ((size_t)(b*SS + r0 + 8) * FF + qf) * DD + h * CC;
#pragma unroll
        for (int kc = 0; kc < 8; kc++) {
            qa[kc][0] = __float_as_uint(to_tf32(Qg[base0 + kc*8 + ct    ] * 0.125f));
            qa[kc][1] = __float_as_uint(to_tf32(Qg[base1 + kc*8 + ct    ] * 0.125f));
            qa[kc][2] = __float_as_uint(to_tf32(Qg[base0 + kc*8 + ct + 4] * 0.125f));
            qa[kc][3] = __float_as_uint(to_tf32(Qg[base1 + kc*8 + ct + 4] * 0.125f));
        }
    }

    float o[8][4];
#pragma unroll
    for (int nf = 0; nf < 8; nf++)
#pragma unroll
        for (int r = 0; r < 4; r++) o[nf][r] = 0.f;
    float m0 = -1e30f, m1 = -1e30f, l0 = 0.f, l1 = 0.f;

    // K/V tile load assignment: 2 threads per key row, 32 c each
    const int key   = tid >> 1;
    const int chalf = (tid & 1) * 32;

    for (int kt = 0; kt < n_tiles; kt++) {
        __syncthreads();   // previous tile's P/V reads complete
        {
            int kg = kt * 64 + key;
            int sk, fk;
            if (MODE == 0) { sk = kg; fk = f; }
            else           { sk = kg / df; fk = g_frames[b][kg - sk*df]; }
            size_t krow = ((size_t)(b*SS + sk) * FF + fk) * DD + h * CC + chalf;
#pragma unroll
            for (int u = 0; u < 8; u++) {
                int c = chalf + u * 4;
                float4 tk = *(const float4*)&Kg[krow + u*4];
                KPs[c+0][key] = to_tf32(tk.x); KPs[c+1][key] = to_tf32(tk.y);
                KPs[c+2][key] = to_tf32(tk.z); KPs[c+3][key] = to_tf32(tk.w);
                float4 tv = *(const float4*)&Vg[krow + u*4];
                tv.x = to_tf32(tv.x); tv.y = to_tf32(tv.y);
                tv.z = to_tf32(tv.z); tv.w = to_tf32(tv.w);
                *(float4*)&Vs[key][c] = tv;
            }
        }
        __syncthreads();

        // S = (Q*sc) K^T, 16x64 per warp
        float s[8][4];
#pragma unroll
        for (int nf = 0; nf < 8; nf++)
#pragma unroll
            for (int r = 0; r < 4; r++) s[nf][r] = 0.f;
#pragma unroll
        for (int kc = 0; kc < 8; kc++) {
#pragma unroll
            for (int nf = 0; nf < 8; nf++) {
                uint32_t bfr[2];
                bfr[0] = __float_as_uint(KPs[kc*8 + ct    ][nf*8 + gID]);
                bfr[1] = __float_as_uint(KPs[kc*8 + ct + 4][nf*8 + gID]);
                mma_tf32(s[nf], qa[kc], bfr);
            }
        }

        // Online softmax: rows gID (regs 0,1) and gID+8 (regs 2,3)
        float mx0 = -1e30f, mx1 = -1e30f;
#pragma unroll
        for (int nf = 0; nf < 8; nf++) {
            mx0 = fmaxf(mx0, fmaxf(s[nf][0], s[nf][1]));
            mx1 = fmaxf(mx1, fmaxf(s[nf][2], s[nf][3]));
        }
        mx0 = fmaxf(mx0, __shfl_xor_sync(0xffffffffu, mx0, 1));
        mx0 = fmaxf(mx0, __shfl_xor_sync(0xffffffffu, mx0, 2));
        mx1 = fmaxf(mx1, __shfl_xor_sync(0xffffffffu, mx1, 1));
        mx1 = fmaxf(mx1, __shfl_xor_sync(0xffffffffu, mx1, 2));

        float m0n = fmaxf(m0, mx0), m1n = fmaxf(m1, mx1);
        float a0 = __expf(m0 - m0n), a1 = __expf(m1 - m1n);
        float s0 = 0.f, s1 = 0.f;
#pragma unroll
        for (int nf = 0; nf < 8; nf++) {
            s[nf][0] = __expf(s[nf][0] - m0n);
            s[nf][1] = __expf(s[nf][1] - m0n);
            s[nf][2] = __expf(s[nf][2] - m1n);
            s[nf][3] = __expf(s[nf][3] - m1n);
            s0 += s[nf][0] + s[nf][1];
            s1 += s[nf][2] + s[nf][3];
        }
        s0 += __shfl_xor_sync(0xffffffffu, s0, 1);
        s0 += __shfl_xor_sync(0xffffffffu, s0, 2);
        s1 += __shfl_xor_sync(0xffffffffu, s1, 1);
        s1 += __shfl_xor_sync(0xffffffffu, s1, 2);
        l0 = l0 * a0 + s0; m0 = m0n;
        l1 = l1 * a1 + s1; m1 = m1n;
#pragma unroll
        for (int nf = 0; nf < 8; nf++) {
            o[nf][0] *= a0; o[nf][1] *= a0;
            o[nf][2] *= a1; o[nf][3] *= a1;
        }

        __syncthreads();   // all warps finished reading KPs as K

        // Store P (tf32) into KPs as [q][k]; each warp writes its own rows.
        const int pr0 = w * 16 + gID, pr1 = pr0 + 8;
#pragma unroll
        for (int nf = 0; nf < 8; nf++) {
            int col = nf * 8 + ct * 2;
            float2 v0 = make_float2(to_tf32(s[nf][0]), to_tf32(s[nf][1]));
            float2 v1 = make_float2(to_tf32(s[nf][2]), to_tf32(s[nf][3]));
            *(float2*)&KPs[pr0][col] = v0;
            *(float2*)&KPs[pr1][col] = v1;
        }
        // No sync needed: each warp reads back only the rows it wrote.

        // O += P @ V
#pragma unroll
        for (int kc = 0; kc < 8; kc++) {
            uint32_t pa[4];
            pa[0] = __float_as_uint(KPs[pr0][kc*8 + ct    ]);
            pa[1] = __float_as_uint(KPs[pr1][kc*8 + ct    ]);
            pa[2] = __float_as_uint(KPs[pr0][kc*8 + ct + 4]);
            pa[3] = __float_as_uint(KPs[pr1][kc*8 + ct + 4]);
#pragma unroll
            for (int nf = 0; nf < 8; nf++) {
                uint32_t bfr[2];
                bfr[0] = __float_as_uint(Vs[kc*8 + ct    ][nf*8 + gID]);
                bfr[1] = __float_as_uint(Vs[kc*8 + ct + 4][nf*8 + gID]);
                mma_tf32(o[nf], pa, bfr);
            }
        }
    }

    // Epilogue: normalize and write to output frame slot
    const int of = (MODE == 0) ? f : 0;
    const float inv0 = 1.0f / l0, inv1 = 1.0f / l1;
    const int r0 = q0 + w * 16 + gID;
    const size_t ob0 = ((size_t)(b*SS + r0    ) * FF + of) * DD + h * CC;
    const size_t ob1 = ((size_t)(b*SS + r0 + 8) * FF + of) * DD + h * CC;
#pragma unroll
    for (int nf = 0; nf < 8; nf++) {
        int col = nf * 8 + ct * 2;
        *(float2*)&Og[ob0 + col] = make_float2(o[nf][0] * inv0, o[nf][1] * inv0);
        *(float2*)&Og[ob1 + col] = make_float2(o[nf][2] * inv1, o[nf][3] * inv1);
    }
}

// ---------------------------------------------------------------------------
// kernel_launch: graph-capturable sequence on the default stream.
// ---------------------------------------------------------------------------
extern "C" void kernel_launch(void* const* d_in, const int* in_sizes, int n_in,
                              void* d_out, int out_size)
{
    const float* x    = (const float*)d_in[0];
    const int*   mask = (const int*)  d_in[1];   // drop_mask (int32)
    const float* Wq   = (const float*)d_in[2];
    const float* Wk   = (const float*)d_in[3];
    const float* Wv   = (const float*)d_in[4];
    const float* Wout = (const float*)d_in[5];
    const float* bout = (const float*)d_in[6];
    float* out = (float*)d_out;

    float *q, *k, *v, *att;
    cudaGetSymbolAddress((void**)&q,   g_q);
    cudaGetSymbolAddress((void**)&k,   g_k);
    cudaGetSymbolAddress((void**)&v,   g_v);
    cudaGetSymbolAddress((void**)&att, g_att);

    build_frames_kernel<<<1, 32>>>(mask);

    dim3 ggrid(MROWS / 128, DD / 128);   // (144, 4)
    gemm_tf32_kernel<<<ggrid, 256>>>(x, Wq, q, nullptr);
    gemm_tf32_kernel<<<ggrid, 256>>>(x, Wk, k, nullptr);
    gemm_tf32_kernel<<<ggrid, 256>>>(x, Wv, v, nullptr);

    // ress: per-frame self attention, frames 1..15
    attn_mma_kernel<0><<<dim3(SS / 64, BB * (FF-1) * HH), 128>>>(q, k, v, att);
    // resq: frame-0 queries over gathered key/value frames
    attn_mma_kernel<1><<<dim3(SS / 64, BB * HH), 128>>>(q, k, v, att);

    // output projection + bias
    gemm_tf32_kernel<<<ggrid, 256>>>(att, Wout, out, bout);
}